// round 1
// baseline (speedup 1.0000x reference)
#include <cuda_runtime.h>
#include <math.h>

#define NB 4
#define NS 2048
#define ND 1024
#define NH 16
#define NDK 64
#define NM (NB*NS)

// Scratch (device globals: allocation-free rule)
__device__ float g_q[(size_t)NM*ND];
__device__ float g_k[(size_t)NM*ND];
__device__ float g_v[(size_t)NM*ND];
__device__ float g_o[(size_t)NM*ND];
__device__ float g_cos[NS*(NDK/2)];
__device__ float g_sin[NS*(NDK/2)];

// ---------------------------------------------------------------------------
// RoPE cos/sin table (double precision internally for accuracy)
// ---------------------------------------------------------------------------
__global__ void rope_table_kernel() {
    int idx = blockIdx.x * blockDim.x + threadIdx.x;
    if (idx >= NS * 32) return;
    int s = idx >> 5;
    int i = idx & 31;
    double freq = exp(-((double)(2 * i) / (double)NDK) * log(10000.0));
    double ang = (double)s * freq;
    g_cos[idx] = (float)cos(ang);
    g_sin[idx] = (float)sin(ang);
}

// ---------------------------------------------------------------------------
// NT GEMM: C[m,n] = sum_k A[m,k] * Wt[n,k].  M=8192, N=1024, K=1024.
// BM=BN=128, BK=16, 256 threads, 8x8 per thread.
// ROPE=1: apply interleaved RoPE to output (Q/K projections).
// ---------------------------------------------------------------------------
template<int ROPE>
__global__ __launch_bounds__(256) void gemm_nt(const float* __restrict__ A,
                                               const float* __restrict__ Wt,
                                               float* __restrict__ C) {
    __shared__ float As[16][132];
    __shared__ float Bs[16][132];
    const int tid = threadIdx.x;
    const int bm = blockIdx.y * 128;
    const int bn = blockIdx.x * 128;
    const int ty = tid >> 4;
    const int tx = tid & 15;
    const int lrow = tid >> 2;          // 0..63
    const int lk   = (tid & 3) << 2;    // 0,4,8,12

    float acc[8][8];
    #pragma unroll
    for (int i = 0; i < 8; i++)
        #pragma unroll
        for (int j = 0; j < 8; j++) acc[i][j] = 0.0f;

    for (int k0 = 0; k0 < ND; k0 += 16) {
        #pragma unroll
        for (int half = 0; half < 2; half++) {
            int row = lrow + half * 64;
            float4 a4 = *(const float4*)(A  + (size_t)(bm + row) * ND + k0 + lk);
            As[lk + 0][row] = a4.x;
            As[lk + 1][row] = a4.y;
            As[lk + 2][row] = a4.z;
            As[lk + 3][row] = a4.w;
            float4 b4 = *(const float4*)(Wt + (size_t)(bn + row) * ND + k0 + lk);
            Bs[lk + 0][row] = b4.x;
            Bs[lk + 1][row] = b4.y;
            Bs[lk + 2][row] = b4.z;
            Bs[lk + 3][row] = b4.w;
        }
        __syncthreads();
        #pragma unroll
        for (int kk = 0; kk < 16; kk++) {
            float a[8], b[8];
            #pragma unroll
            for (int j = 0; j < 8; j++) a[j] = As[kk][ty * 8 + j];
            #pragma unroll
            for (int j = 0; j < 8; j++) b[j] = Bs[kk][tx * 8 + j];
            #pragma unroll
            for (int i = 0; i < 8; i++)
                #pragma unroll
                for (int j = 0; j < 8; j++)
                    acc[i][j] = fmaf(a[i], b[j], acc[i][j]);
        }
        __syncthreads();
    }

    // epilogue (+ optional fused RoPE)
    #pragma unroll
    for (int i = 0; i < 8; i++) {
        int m = bm + ty * 8 + i;
        int s = m & (NS - 1);
        if (ROPE) {
            #pragma unroll
            for (int j = 0; j < 8; j += 2) {
                int n = bn + tx * 8 + j;
                int ip = (n & 63) >> 1;
                float c  = g_cos[s * 32 + ip];
                float sn = g_sin[s * 32 + ip];
                float x1 = acc[i][j];
                float x2 = acc[i][j + 1];
                acc[i][j]     = x1 * c - x2 * sn;
                acc[i][j + 1] = x1 * sn + x2 * c;
            }
        }
        float* crow = C + (size_t)m * ND + bn + tx * 8;
        *(float4*)(crow)     = make_float4(acc[i][0], acc[i][1], acc[i][2], acc[i][3]);
        *(float4*)(crow + 4) = make_float4(acc[i][4], acc[i][5], acc[i][6], acc[i][7]);
    }
}

// ---------------------------------------------------------------------------
// Causal flash attention. grid = (S/64, H, B), 256 threads.
// 64 queries x 64 keys tiles, DK=64. Online softmax.
// SMEM: Qs[q][d], Kt[d][k] (transposed), Vs[k][dc], Ps[q][k], stride 68.
// ---------------------------------------------------------------------------
#define FA_STRIDE 68
#define FA_SMEM (4 * 64 * FA_STRIDE * (int)sizeof(float))

__global__ __launch_bounds__(256) void flash_attn_kernel() {
    extern __shared__ float sm[];
    float* Qs = sm;
    float* Kt = sm + 64 * FA_STRIDE;
    float* Vs = sm + 2 * 64 * FA_STRIDE;
    float* Ps = sm + 3 * 64 * FA_STRIDE;

    const int qblk = blockIdx.x;
    const int h    = blockIdx.y;
    const int b    = blockIdx.z;
    const int q0   = qblk * 64;
    const int tid  = threadIdx.x;
    const int tr   = tid >> 4;   // 0..15 -> q rows tr*4..+3
    const int tc   = tid & 15;   // 0..15 -> k/dk cols tc*4..+3
    const size_t headoff = (size_t)h * NDK;

    // load Q tile
    for (int l = tid; l < 64 * 16; l += 256) {
        int r  = l >> 4;
        int cv = (l & 15) << 2;
        float4 v = *(const float4*)(g_q + ((size_t)(b * NS + q0 + r)) * ND + headoff + cv);
        *(float4*)(Qs + r * FA_STRIDE + cv) = v;
    }

    float m_i[4], l_i[4], acc[4][4];
    #pragma unroll
    for (int i = 0; i < 4; i++) {
        m_i[i] = -1e30f;
        l_i[i] = 0.0f;
        #pragma unroll
        for (int j = 0; j < 4; j++) acc[i][j] = 0.0f;
    }
    __syncthreads();

    const int nk = qblk + 1;
    for (int kt = 0; kt < nk; kt++) {
        const int k0 = kt * 64;
        // load K (transposed) and V
        for (int l = tid; l < 64 * 16; l += 256) {
            int r  = l >> 4;
            int cv = (l & 15) << 2;
            size_t gidx = ((size_t)(b * NS + k0 + r)) * ND + headoff + cv;
            float4 kv = *(const float4*)(g_k + gidx);
            Kt[(cv + 0) * FA_STRIDE + r] = kv.x;
            Kt[(cv + 1) * FA_STRIDE + r] = kv.y;
            Kt[(cv + 2) * FA_STRIDE + r] = kv.z;
            Kt[(cv + 3) * FA_STRIDE + r] = kv.w;
            *(float4*)(Vs + r * FA_STRIDE + cv) = *(const float4*)(g_v + gidx);
        }
        __syncthreads();

        // scores: sc[i][j] = Q[tr*4+i] . K[tc*4+j]
        float sc[4][4];
        #pragma unroll
        for (int i = 0; i < 4; i++)
            #pragma unroll
            for (int j = 0; j < 4; j++) sc[i][j] = 0.0f;

        #pragma unroll 4
        for (int d = 0; d < 64; d++) {
            float4 bb = *(const float4*)(Kt + d * FA_STRIDE + tc * 4);
            #pragma unroll
            for (int i = 0; i < 4; i++) {
                float a = Qs[(tr * 4 + i) * FA_STRIDE + d];
                sc[i][0] = fmaf(a, bb.x, sc[i][0]);
                sc[i][1] = fmaf(a, bb.y, sc[i][1]);
                sc[i][2] = fmaf(a, bb.z, sc[i][2]);
                sc[i][3] = fmaf(a, bb.w, sc[i][3]);
            }
        }

        const float scale = 0.125f;
        if (kt == nk - 1) {
            #pragma unroll
            for (int i = 0; i < 4; i++) {
                int qg = q0 + tr * 4 + i;
                #pragma unroll
                for (int j = 0; j < 4; j++) {
                    int kg = k0 + tc * 4 + j;
                    sc[i][j] = (kg <= qg) ? sc[i][j] * scale : -1e30f;
                }
            }
        } else {
            #pragma unroll
            for (int i = 0; i < 4; i++)
                #pragma unroll
                for (int j = 0; j < 4; j++) sc[i][j] *= scale;
        }

        // online softmax update
        #pragma unroll
        for (int i = 0; i < 4; i++) {
            float mt = fmaxf(fmaxf(sc[i][0], sc[i][1]), fmaxf(sc[i][2], sc[i][3]));
            mt = fmaxf(mt, __shfl_xor_sync(0xffffffffu, mt, 8));
            mt = fmaxf(mt, __shfl_xor_sync(0xffffffffu, mt, 4));
            mt = fmaxf(mt, __shfl_xor_sync(0xffffffffu, mt, 2));
            mt = fmaxf(mt, __shfl_xor_sync(0xffffffffu, mt, 1));
            float mnew  = fmaxf(m_i[i], mt);
            float alpha = __expf(m_i[i] - mnew);
            float rs = 0.0f;
            #pragma unroll
            for (int j = 0; j < 4; j++) {
                sc[i][j] = __expf(sc[i][j] - mnew);
                rs += sc[i][j];
            }
            rs += __shfl_xor_sync(0xffffffffu, rs, 8);
            rs += __shfl_xor_sync(0xffffffffu, rs, 4);
            rs += __shfl_xor_sync(0xffffffffu, rs, 2);
            rs += __shfl_xor_sync(0xffffffffu, rs, 1);
            l_i[i] = l_i[i] * alpha + rs;
            m_i[i] = mnew;
            #pragma unroll
            for (int j = 0; j < 4; j++) acc[i][j] *= alpha;
            *(float4*)(Ps + (tr * 4 + i) * FA_STRIDE + tc * 4) =
                make_float4(sc[i][0], sc[i][1], sc[i][2], sc[i][3]);
        }
        __syncthreads();

        // O += P * V
        #pragma unroll 4
        for (int k = 0; k < 64; k++) {
            float4 vv = *(const float4*)(Vs + k * FA_STRIDE + tc * 4);
            #pragma unroll
            for (int i = 0; i < 4; i++) {
                float p = Ps[(tr * 4 + i) * FA_STRIDE + k];
                acc[i][0] = fmaf(p, vv.x, acc[i][0]);
                acc[i][1] = fmaf(p, vv.y, acc[i][1]);
                acc[i][2] = fmaf(p, vv.z, acc[i][2]);
                acc[i][3] = fmaf(p, vv.w, acc[i][3]);
            }
        }
        __syncthreads();
    }

    // write O
    #pragma unroll
    for (int i = 0; i < 4; i++) {
        float inv = 1.0f / l_i[i];
        float4 o = make_float4(acc[i][0] * inv, acc[i][1] * inv,
                               acc[i][2] * inv, acc[i][3] * inv);
        *(float4*)(g_o + ((size_t)(b * NS + q0 + tr * 4 + i)) * ND + headoff + tc * 4) = o;
    }
}

// ---------------------------------------------------------------------------
extern "C" void kernel_launch(void* const* d_in, const int* in_sizes, int n_in,
                              void* d_out, int out_size) {
    const float* x  = (const float*)d_in[0];
    // d_in[1] = mask (bool tril) -- causality is hardcoded
    const float* wq = (const float*)d_in[2];
    const float* wk = (const float*)d_in[3];
    const float* wv = (const float*)d_in[4];
    const float* wo = (const float*)d_in[5];
    float* out = (float*)d_out;

    void *pq, *pk, *pv, *po;
    cudaGetSymbolAddress(&pq, g_q);
    cudaGetSymbolAddress(&pk, g_k);
    cudaGetSymbolAddress(&pv, g_v);
    cudaGetSymbolAddress(&po, g_o);

    cudaFuncSetAttribute(flash_attn_kernel,
                         cudaFuncAttributeMaxDynamicSharedMemorySize, FA_SMEM);

    rope_table_kernel<<<(NS * 32 + 255) / 256, 256>>>();

    dim3 gg(ND / 128, NM / 128);
    gemm_nt<1><<<gg, 256>>>(x, wq, (float*)pq);
    gemm_nt<1><<<gg, 256>>>(x, wk, (float*)pk);
    gemm_nt<0><<<gg, 256>>>(x, wv, (float*)pv);

    flash_attn_kernel<<<dim3(NS / 64, NH, NB), 256, FA_SMEM>>>();

    gemm_nt<0><<<gg, 256>>>((const float*)po, wo, out);
}

// round 3
// speedup vs baseline: 2.6178x; 2.6178x over previous
#include <cuda_runtime.h>
#include <math.h>

#define NB 4
#define NS 2048
#define ND 1024
#define NH 16
#define NDK 64
#define NM (NB*NS)

// Scratch (device globals: allocation-free rule)
__device__ float g_q[(size_t)NM*ND];
__device__ float g_k[(size_t)NM*ND];
__device__ float g_v[(size_t)NM*ND];
__device__ float g_o[(size_t)NM*ND];
__device__ float g_cos[NS*(NDK/2)];
__device__ float g_sin[NS*(NDK/2)];

// ---------------------------------------------------------------------------
// RoPE cos/sin table (double precision internally for accuracy)
// ---------------------------------------------------------------------------
__global__ void rope_table_kernel() {
    int idx = blockIdx.x * blockDim.x + threadIdx.x;
    if (idx >= NS * 32) return;
    int s = idx >> 5;
    int i = idx & 31;
    double freq = exp(-((double)(2 * i) / (double)NDK) * log(10000.0));
    double ang = (double)s * freq;
    g_cos[idx] = (float)cos(ang);
    g_sin[idx] = (float)sin(ang);
}

// ---------------------------------------------------------------------------
// tf32 helpers
// ---------------------------------------------------------------------------
__device__ __forceinline__ unsigned f2tf32(float x) {
    unsigned r;
    asm("cvt.rna.tf32.f32 %0, %1;" : "=r"(r) : "f"(x));
    return r;
}

__device__ __forceinline__ void mma_tf32(float* c, const unsigned* a, const unsigned* b) {
    asm volatile("mma.sync.aligned.m16n8k8.row.col.f32.tf32.tf32.f32 "
                 "{%0,%1,%2,%3}, {%4,%5,%6,%7}, {%8,%9}, {%0,%1,%2,%3};"
                 : "+f"(c[0]), "+f"(c[1]), "+f"(c[2]), "+f"(c[3])
                 : "r"(a[0]), "r"(a[1]), "r"(a[2]), "r"(a[3]),
                   "r"(b[0]), "r"(b[1]));
}

// ---------------------------------------------------------------------------
// Tensor-core NT GEMM (tf32): C[m,n] = sum_k A[m,k] * Wt[n,k].
// M=8192 (or 8192), N=1024, K=1024.  BM=BN=128, BK=32.
// 8 warps in 2x4 grid; warp tile 64x32; 4x4 m16n8k8 tiles per warp.
// ROPE=1: fused interleaved RoPE on output (Q/K projections).
// ---------------------------------------------------------------------------
template<int ROPE>
__global__ __launch_bounds__(256) void gemm_tc(const float* __restrict__ A,
                                               const float* __restrict__ Wt,
                                               float* __restrict__ C) {
    __shared__ float As[128][36];
    __shared__ float Bs[128][36];

    const int tid  = threadIdx.x;
    const int warp = tid >> 5;
    const int lane = tid & 31;
    const int wm   = warp >> 2;     // 0..1
    const int wn   = warp & 3;      // 0..3
    const int gid  = lane >> 2;     // 0..7
    const int tig  = lane & 3;      // 0..3
    const int bm   = blockIdx.y * 128;
    const int bn   = blockIdx.x * 128;

    float acc[4][4][4];
    #pragma unroll
    for (int mt = 0; mt < 4; mt++)
        #pragma unroll
        for (int nt = 0; nt < 4; nt++)
            #pragma unroll
            for (int c = 0; c < 4; c++) acc[mt][nt][c] = 0.0f;

    for (int k0 = 0; k0 < ND; k0 += 32) {
        #pragma unroll
        for (int i = 0; i < 4; i++) {
            int idx = i * 256 + tid;
            int r = idx >> 3;
            int c = (idx & 7) << 2;
            *(float4*)(&As[r][c]) = *(const float4*)(A  + (size_t)(bm + r) * ND + k0 + c);
            *(float4*)(&Bs[r][c]) = *(const float4*)(Wt + (size_t)(bn + r) * ND + k0 + c);
        }
        __syncthreads();

        #pragma unroll
        for (int ks = 0; ks < 32; ks += 8) {
            unsigned af[4][4], bf[4][2];
            #pragma unroll
            for (int mt = 0; mt < 4; mt++) {
                int r = wm * 64 + mt * 16 + gid;
                af[mt][0] = f2tf32(As[r    ][ks + tig]);
                af[mt][1] = f2tf32(As[r + 8][ks + tig]);
                af[mt][2] = f2tf32(As[r    ][ks + tig + 4]);
                af[mt][3] = f2tf32(As[r + 8][ks + tig + 4]);
            }
            #pragma unroll
            for (int nt = 0; nt < 4; nt++) {
                int n = wn * 32 + nt * 8 + gid;
                bf[nt][0] = f2tf32(Bs[n][ks + tig]);
                bf[nt][1] = f2tf32(Bs[n][ks + tig + 4]);
            }
            #pragma unroll
            for (int mt = 0; mt < 4; mt++)
                #pragma unroll
                for (int nt = 0; nt < 4; nt++)
                    mma_tf32(acc[mt][nt], af[mt], bf[nt]);
        }
        __syncthreads();
    }

    // epilogue (+ optional fused RoPE).  c0,c1 at (m, n..n+1); c2,c3 at (m+8, n..n+1)
    #pragma unroll
    for (int mt = 0; mt < 4; mt++) {
        int m0 = bm + wm * 64 + mt * 16 + gid;
        #pragma unroll
        for (int nt = 0; nt < 4; nt++) {
            int n = bn + wn * 32 + nt * 8 + 2 * tig;
            float c0 = acc[mt][nt][0], c1 = acc[mt][nt][1];
            float c2 = acc[mt][nt][2], c3 = acc[mt][nt][3];
            if (ROPE) {
                int ip = (n & 63) >> 1;
                int s0 = m0 & (NS - 1);
                int s1 = (m0 + 8) & (NS - 1);
                float ca = g_cos[s0 * 32 + ip], sa = g_sin[s0 * 32 + ip];
                float cb = g_cos[s1 * 32 + ip], sb = g_sin[s1 * 32 + ip];
                float t0 = c0 * ca - c1 * sa;
                float t1 = c0 * sa + c1 * ca;
                float t2 = c2 * cb - c3 * sb;
                float t3 = c2 * sb + c3 * cb;
                c0 = t0; c1 = t1; c2 = t2; c3 = t3;
            }
            *(float2*)(C + (size_t)m0 * ND + n)       = make_float2(c0, c1);
            *(float2*)(C + (size_t)(m0 + 8) * ND + n) = make_float2(c2, c3);
        }
    }
}

// ---------------------------------------------------------------------------
// Causal flash attention. grid = (S/64, H, B), 256 threads.
// 64 queries x 64 keys tiles, DK=64. Online softmax.
// ---------------------------------------------------------------------------
#define FA_STRIDE 68
#define FA_SMEM (4 * 64 * FA_STRIDE * (int)sizeof(float))

__global__ __launch_bounds__(256) void flash_attn_kernel() {
    extern __shared__ float sm[];
    float* Qs = sm;
    float* Kt = sm + 64 * FA_STRIDE;
    float* Vs = sm + 2 * 64 * FA_STRIDE;
    float* Ps = sm + 3 * 64 * FA_STRIDE;

    const int qblk = blockIdx.x;
    const int h    = blockIdx.y;
    const int b    = blockIdx.z;
    const int q0   = qblk * 64;
    const int tid  = threadIdx.x;
    const int tr   = tid >> 4;
    const int tc   = tid & 15;
    const size_t headoff = (size_t)h * NDK;

    for (int l = tid; l < 64 * 16; l += 256) {
        int r  = l >> 4;
        int cv = (l & 15) << 2;
        float4 v = *(const float4*)(g_q + ((size_t)(b * NS + q0 + r)) * ND + headoff + cv);
        *(float4*)(Qs + r * FA_STRIDE + cv) = v;
    }

    float m_i[4], l_i[4], acc[4][4];
    #pragma unroll
    for (int i = 0; i < 4; i++) {
        m_i[i] = -1e30f;
        l_i[i] = 0.0f;
        #pragma unroll
        for (int j = 0; j < 4; j++) acc[i][j] = 0.0f;
    }
    __syncthreads();

    const int nk = qblk + 1;
    for (int kt = 0; kt < nk; kt++) {
        const int k0 = kt * 64;
        for (int l = tid; l < 64 * 16; l += 256) {
            int r  = l >> 4;
            int cv = (l & 15) << 2;
            size_t gidx = ((size_t)(b * NS + k0 + r)) * ND + headoff + cv;
            float4 kv = *(const float4*)(g_k + gidx);
            Kt[(cv + 0) * FA_STRIDE + r] = kv.x;
            Kt[(cv + 1) * FA_STRIDE + r] = kv.y;
            Kt[(cv + 2) * FA_STRIDE + r] = kv.z;
            Kt[(cv + 3) * FA_STRIDE + r] = kv.w;
            *(float4*)(Vs + r * FA_STRIDE + cv) = *(const float4*)(g_v + gidx);
        }
        __syncthreads();

        float sc[4][4];
        #pragma unroll
        for (int i = 0; i < 4; i++)
            #pragma unroll
            for (int j = 0; j < 4; j++) sc[i][j] = 0.0f;

        #pragma unroll 4
        for (int d = 0; d < 64; d++) {
            float4 bb = *(const float4*)(Kt + d * FA_STRIDE + tc * 4);
            #pragma unroll
            for (int i = 0; i < 4; i++) {
                float a = Qs[(tr * 4 + i) * FA_STRIDE + d];
                sc[i][0] = fmaf(a, bb.x, sc[i][0]);
                sc[i][1] = fmaf(a, bb.y, sc[i][1]);
                sc[i][2] = fmaf(a, bb.z, sc[i][2]);
                sc[i][3] = fmaf(a, bb.w, sc[i][3]);
            }
        }

        const float scale = 0.125f;
        if (kt == nk - 1) {
            #pragma unroll
            for (int i = 0; i < 4; i++) {
                int qg = q0 + tr * 4 + i;
                #pragma unroll
                for (int j = 0; j < 4; j++) {
                    int kg = k0 + tc * 4 + j;
                    sc[i][j] = (kg <= qg) ? sc[i][j] * scale : -1e30f;
                }
            }
        } else {
            #pragma unroll
            for (int i = 0; i < 4; i++)
                #pragma unroll
                for (int j = 0; j < 4; j++) sc[i][j] *= scale;
        }

        #pragma unroll
        for (int i = 0; i < 4; i++) {
            float mt = fmaxf(fmaxf(sc[i][0], sc[i][1]), fmaxf(sc[i][2], sc[i][3]));
            mt = fmaxf(mt, __shfl_xor_sync(0xffffffffu, mt, 8));
            mt = fmaxf(mt, __shfl_xor_sync(0xffffffffu, mt, 4));
            mt = fmaxf(mt, __shfl_xor_sync(0xffffffffu, mt, 2));
            mt = fmaxf(mt, __shfl_xor_sync(0xffffffffu, mt, 1));
            float mnew  = fmaxf(m_i[i], mt);
            float alpha = __expf(m_i[i] - mnew);
            float rs = 0.0f;
            #pragma unroll
            for (int j = 0; j < 4; j++) {
                sc[i][j] = __expf(sc[i][j] - mnew);
                rs += sc[i][j];
            }
            rs += __shfl_xor_sync(0xffffffffu, rs, 8);
            rs += __shfl_xor_sync(0xffffffffu, rs, 4);
            rs += __shfl_xor_sync(0xffffffffu, rs, 2);
            rs += __shfl_xor_sync(0xffffffffu, rs, 1);
            l_i[i] = l_i[i] * alpha + rs;
            m_i[i] = mnew;
            #pragma unroll
            for (int j = 0; j < 4; j++) acc[i][j] *= alpha;
            *(float4*)(Ps + (tr * 4 + i) * FA_STRIDE + tc * 4) =
                make_float4(sc[i][0], sc[i][1], sc[i][2], sc[i][3]);
        }
        __syncthreads();

        #pragma unroll 4
        for (int k = 0; k < 64; k++) {
            float4 vv = *(const float4*)(Vs + k * FA_STRIDE + tc * 4);
            #pragma unroll
            for (int i = 0; i < 4; i++) {
                float p = Ps[(tr * 4 + i) * FA_STRIDE + k];
                acc[i][0] = fmaf(p, vv.x, acc[i][0]);
                acc[i][1] = fmaf(p, vv.y, acc[i][1]);
                acc[i][2] = fmaf(p, vv.z, acc[i][2]);
                acc[i][3] = fmaf(p, vv.w, acc[i][3]);
            }
        }
        __syncthreads();
    }

    #pragma unroll
    for (int i = 0; i < 4; i++) {
        float inv = 1.0f / l_i[i];
        float4 o = make_float4(acc[i][0] * inv, acc[i][1] * inv,
                               acc[i][2] * inv, acc[i][3] * inv);
        *(float4*)(g_o + ((size_t)(b * NS + q0 + tr * 4 + i)) * ND + headoff + tc * 4) = o;
    }
}

// ---------------------------------------------------------------------------
extern "C" void kernel_launch(void* const* d_in, const int* in_sizes, int n_in,
                              void* d_out, int out_size) {
    const float* x  = (const float*)d_in[0];
    // d_in[1] = mask (bool tril) -- causality is hardcoded
    const float* wq = (const float*)d_in[2];
    const float* wk = (const float*)d_in[3];
    const float* wv = (const float*)d_in[4];
    const float* wo = (const float*)d_in[5];
    float* out = (float*)d_out;

    void *pq, *pk, *pv, *po;
    cudaGetSymbolAddress(&pq, g_q);
    cudaGetSymbolAddress(&pk, g_k);
    cudaGetSymbolAddress(&pv, g_v);
    cudaGetSymbolAddress(&po, g_o);

    cudaFuncSetAttribute(flash_attn_kernel,
                         cudaFuncAttributeMaxDynamicSharedMemorySize, FA_SMEM);

    rope_table_kernel<<<(NS * 32 + 255) / 256, 256>>>();

    dim3 gg(ND / 128, NM / 128);
    gemm_tc<1><<<gg, 256>>>(x, wq, (float*)pq);
    gemm_tc<1><<<gg, 256>>>(x, wk, (float*)pk);
    gemm_tc<0><<<gg, 256>>>(x, wv, (float*)pv);

    flash_attn_kernel<<<dim3(NS / 64, NH, NB), 256, FA_SMEM>>>();

    gemm_tc<0><<<gg, 256>>>((const float*)po, wo, out);
}

// round 4
// speedup vs baseline: 4.5194x; 1.7264x over previous
#include <cuda_runtime.h>
#include <math.h>

#define NB 4
#define NS 2048
#define ND 1024
#define NH 16
#define NDK 64
#define NM (NB*NS)

// Scratch (device globals: allocation-free rule)
__device__ float g_q[(size_t)NM*ND];
__device__ float g_k[(size_t)NM*ND];
__device__ float g_v[(size_t)NM*ND];
__device__ float g_o[(size_t)NM*ND];
__device__ float g_cos[NS*(NDK/2)];
__device__ float g_sin[NS*(NDK/2)];

// ---------------------------------------------------------------------------
// RoPE cos/sin table (double precision internally for accuracy)
// ---------------------------------------------------------------------------
__global__ void rope_table_kernel() {
    int idx = blockIdx.x * blockDim.x + threadIdx.x;
    if (idx >= NS * 32) return;
    int s = idx >> 5;
    int i = idx & 31;
    double freq = exp(-((double)(2 * i) / (double)NDK) * log(10000.0));
    double ang = (double)s * freq;
    g_cos[idx] = (float)cos(ang);
    g_sin[idx] = (float)sin(ang);
}

// ---------------------------------------------------------------------------
// tf32 helpers
// ---------------------------------------------------------------------------
__device__ __forceinline__ unsigned f2tf32(float x) {
    unsigned r;
    asm("cvt.rna.tf32.f32 %0, %1;" : "=r"(r) : "f"(x));
    return r;
}

__device__ __forceinline__ void mma_tf32(float* c, const unsigned* a, const unsigned* b) {
    asm volatile("mma.sync.aligned.m16n8k8.row.col.f32.tf32.tf32.f32 "
                 "{%0,%1,%2,%3}, {%4,%5,%6,%7}, {%8,%9}, {%0,%1,%2,%3};"
                 : "+f"(c[0]), "+f"(c[1]), "+f"(c[2]), "+f"(c[3])
                 : "r"(a[0]), "r"(a[1]), "r"(a[2]), "r"(a[3]),
                   "r"(b[0]), "r"(b[1]));
}

// ---------------------------------------------------------------------------
// Tensor-core NT GEMM (tf32): C[m,n] = sum_k A[m,k] * Wt[n,k].
// BM=BN=128, BK=32. 8 warps; warp tile 64x32; 4x4 m16n8k8 tiles per warp.
// ROPE=1: fused interleaved RoPE on output (Q/K projections).
// ---------------------------------------------------------------------------
template<int ROPE>
__global__ __launch_bounds__(256) void gemm_tc(const float* __restrict__ A,
                                               const float* __restrict__ Wt,
                                               float* __restrict__ C) {
    __shared__ float As[128][36];
    __shared__ float Bs[128][36];

    const int tid  = threadIdx.x;
    const int warp = tid >> 5;
    const int lane = tid & 31;
    const int wm   = warp >> 2;
    const int wn   = warp & 3;
    const int gid  = lane >> 2;
    const int tig  = lane & 3;
    const int bm   = blockIdx.y * 128;
    const int bn   = blockIdx.x * 128;

    float acc[4][4][4];
    #pragma unroll
    for (int mt = 0; mt < 4; mt++)
        #pragma unroll
        for (int nt = 0; nt < 4; nt++)
            #pragma unroll
            for (int c = 0; c < 4; c++) acc[mt][nt][c] = 0.0f;

    for (int k0 = 0; k0 < ND; k0 += 32) {
        #pragma unroll
        for (int i = 0; i < 4; i++) {
            int idx = i * 256 + tid;
            int r = idx >> 3;
            int c = (idx & 7) << 2;
            *(float4*)(&As[r][c]) = *(const float4*)(A  + (size_t)(bm + r) * ND + k0 + c);
            *(float4*)(&Bs[r][c]) = *(const float4*)(Wt + (size_t)(bn + r) * ND + k0 + c);
        }
        __syncthreads();

        #pragma unroll
        for (int ks = 0; ks < 32; ks += 8) {
            unsigned af[4][4], bf[4][2];
            #pragma unroll
            for (int mt = 0; mt < 4; mt++) {
                int r = wm * 64 + mt * 16 + gid;
                af[mt][0] = f2tf32(As[r    ][ks + tig]);
                af[mt][1] = f2tf32(As[r + 8][ks + tig]);
                af[mt][2] = f2tf32(As[r    ][ks + tig + 4]);
                af[mt][3] = f2tf32(As[r + 8][ks + tig + 4]);
            }
            #pragma unroll
            for (int nt = 0; nt < 4; nt++) {
                int n = wn * 32 + nt * 8 + gid;
                bf[nt][0] = f2tf32(Bs[n][ks + tig]);
                bf[nt][1] = f2tf32(Bs[n][ks + tig + 4]);
            }
            #pragma unroll
            for (int mt = 0; mt < 4; mt++)
                #pragma unroll
                for (int nt = 0; nt < 4; nt++)
                    mma_tf32(acc[mt][nt], af[mt], bf[nt]);
        }
        __syncthreads();
    }

    #pragma unroll
    for (int mt = 0; mt < 4; mt++) {
        int m0 = bm + wm * 64 + mt * 16 + gid;
        #pragma unroll
        for (int nt = 0; nt < 4; nt++) {
            int n = bn + wn * 32 + nt * 8 + 2 * tig;
            float c0 = acc[mt][nt][0], c1 = acc[mt][nt][1];
            float c2 = acc[mt][nt][2], c3 = acc[mt][nt][3];
            if (ROPE) {
                int ip = (n & 63) >> 1;
                int s0 = m0 & (NS - 1);
                int s1 = (m0 + 8) & (NS - 1);
                float ca = g_cos[s0 * 32 + ip], sa = g_sin[s0 * 32 + ip];
                float cb = g_cos[s1 * 32 + ip], sb = g_sin[s1 * 32 + ip];
                float t0 = c0 * ca - c1 * sa;
                float t1 = c0 * sa + c1 * ca;
                float t2 = c2 * cb - c3 * sb;
                float t3 = c2 * sb + c3 * cb;
                c0 = t0; c1 = t1; c2 = t2; c3 = t3;
            }
            *(float2*)(C + (size_t)m0 * ND + n)       = make_float2(c0, c1);
            *(float2*)(C + (size_t)(m0 + 8) * ND + n) = make_float2(c2, c3);
        }
    }
}

// ---------------------------------------------------------------------------
// Tensor-core causal flash attention (tf32 mma).
// grid = (S/128, H, B), 256 threads (8 warps x 16 q-rows), 64-key tiles.
// SMEM: Ks[64][FB] (tf32, [kv][d]), Vt[64][FB] (tf32, [d][kv]), Ps[128][FB].
// ---------------------------------------------------------------------------
#define FB 68
#define FA2_SMEM ((64 + 64 + 128) * FB * (int)sizeof(float))

__global__ __launch_bounds__(256, 2) void flash_tc_kernel() {
    extern __shared__ float sm[];
    float* Ks = sm;
    float* Vt = sm + 64 * FB;
    float* Ps = sm + 128 * FB;

    const int tid  = threadIdx.x;
    const int warp = tid >> 5;
    const int lane = tid & 31;
    const int gid  = lane >> 2;
    const int tig  = lane & 3;
    const int q0   = blockIdx.x * 128;
    const int h    = blockIdx.y;
    const int b    = blockIdx.z;
    const size_t base = (size_t)(b * NS) * ND + (size_t)h * NDK;

    // stage Q (pre-scaled by 1/sqrt(DK), tf32) into Ps
    for (int l = tid; l < 128 * 16; l += 256) {
        int r = l >> 4;
        int c = (l & 15) << 2;
        float4 v = *(const float4*)(g_q + base + (size_t)(q0 + r) * ND + c);
        unsigned* dst = (unsigned*)(Ps + r * FB + c);
        dst[0] = f2tf32(v.x * 0.125f);
        dst[1] = f2tf32(v.y * 0.125f);
        dst[2] = f2tf32(v.z * 0.125f);
        dst[3] = f2tf32(v.w * 0.125f);
    }
    __syncthreads();

    unsigned qf[8][4];
    {
        const unsigned* P0 = (const unsigned*)(Ps + (warp * 16 + gid) * FB);
        const unsigned* P1 = (const unsigned*)(Ps + (warp * 16 + gid + 8) * FB);
        #pragma unroll
        for (int ks = 0; ks < 8; ks++) {
            qf[ks][0] = P0[ks * 8 + tig];
            qf[ks][1] = P1[ks * 8 + tig];
            qf[ks][2] = P0[ks * 8 + tig + 4];
            qf[ks][3] = P1[ks * 8 + tig + 4];
        }
    }
    __syncthreads();

    float o[8][4];
    #pragma unroll
    for (int nt = 0; nt < 8; nt++)
        #pragma unroll
        for (int c = 0; c < 4; c++) o[nt][c] = 0.0f;
    float m_a = -1e30f, m_b = -1e30f, l_a = 0.0f, l_b = 0.0f;
    const int row_a = q0 + warp * 16 + gid;
    const int row_b = row_a + 8;
    const int nk = 2 * blockIdx.x + 2;

    for (int kt = 0; kt < nk; kt++) {
        const int k0 = kt * 64;

        // load K tile [kv][d] and V tile transposed [d][kv], tf32-converted
        for (int l = tid; l < 64 * 16; l += 256) {
            int r = l >> 4;
            int c = (l & 15) << 2;
            size_t gidx = base + (size_t)(k0 + r) * ND + c;
            float4 kk = *(const float4*)(g_k + gidx);
            float4 vv = *(const float4*)(g_v + gidx);
            unsigned* kd = (unsigned*)(Ks + r * FB + c);
            kd[0] = f2tf32(kk.x);
            kd[1] = f2tf32(kk.y);
            kd[2] = f2tf32(kk.z);
            kd[3] = f2tf32(kk.w);
            ((unsigned*)Vt)[(c + 0) * FB + r] = f2tf32(vv.x);
            ((unsigned*)Vt)[(c + 1) * FB + r] = f2tf32(vv.y);
            ((unsigned*)Vt)[(c + 2) * FB + r] = f2tf32(vv.z);
            ((unsigned*)Vt)[(c + 3) * FB + r] = f2tf32(vv.w);
        }
        __syncthreads();

        if (k0 <= q0 + warp * 16 + 15) {   // this warp has >=1 valid row in tile
            // S = Q K^T
            float s[8][4];
            #pragma unroll
            for (int nt = 0; nt < 8; nt++)
                #pragma unroll
                for (int c = 0; c < 4; c++) s[nt][c] = 0.0f;

            #pragma unroll
            for (int ks = 0; ks < 8; ks++) {
                #pragma unroll
                for (int nt = 0; nt < 8; nt++) {
                    const unsigned* Kp = (const unsigned*)(Ks + (nt * 8 + gid) * FB + ks * 8);
                    unsigned bf[2] = { Kp[tig], Kp[tig + 4] };
                    mma_tf32(s[nt], qf[ks], bf);
                }
            }

            // causal mask (only tiles touching the diagonal)
            if (k0 + 63 > q0 + warp * 16) {
                #pragma unroll
                for (int nt = 0; nt < 8; nt++) {
                    int kg = k0 + nt * 8 + 2 * tig;
                    if (kg     > row_a) s[nt][0] = -1e30f;
                    if (kg + 1 > row_a) s[nt][1] = -1e30f;
                    if (kg     > row_b) s[nt][2] = -1e30f;
                    if (kg + 1 > row_b) s[nt][3] = -1e30f;
                }
            }

            // online softmax (rows row_a / row_b, replicated across the quad)
            float mx_a = -1e30f, mx_b = -1e30f;
            #pragma unroll
            for (int nt = 0; nt < 8; nt++) {
                mx_a = fmaxf(mx_a, fmaxf(s[nt][0], s[nt][1]));
                mx_b = fmaxf(mx_b, fmaxf(s[nt][2], s[nt][3]));
            }
            mx_a = fmaxf(mx_a, __shfl_xor_sync(0xffffffffu, mx_a, 1));
            mx_a = fmaxf(mx_a, __shfl_xor_sync(0xffffffffu, mx_a, 2));
            mx_b = fmaxf(mx_b, __shfl_xor_sync(0xffffffffu, mx_b, 1));
            mx_b = fmaxf(mx_b, __shfl_xor_sync(0xffffffffu, mx_b, 2));

            float mn_a = fmaxf(m_a, mx_a), mn_b = fmaxf(m_b, mx_b);
            float al_a = __expf(m_a - mn_a), al_b = __expf(m_b - mn_b);
            float rs_a = 0.0f, rs_b = 0.0f;
            #pragma unroll
            for (int nt = 0; nt < 8; nt++) {
                s[nt][0] = __expf(s[nt][0] - mn_a);
                s[nt][1] = __expf(s[nt][1] - mn_a);
                s[nt][2] = __expf(s[nt][2] - mn_b);
                s[nt][3] = __expf(s[nt][3] - mn_b);
                rs_a += s[nt][0] + s[nt][1];
                rs_b += s[nt][2] + s[nt][3];
            }
            rs_a += __shfl_xor_sync(0xffffffffu, rs_a, 1);
            rs_a += __shfl_xor_sync(0xffffffffu, rs_a, 2);
            rs_b += __shfl_xor_sync(0xffffffffu, rs_b, 1);
            rs_b += __shfl_xor_sync(0xffffffffu, rs_b, 2);

            l_a = l_a * al_a + rs_a;
            l_b = l_b * al_b + rs_b;
            m_a = mn_a;
            m_b = mn_b;

            #pragma unroll
            for (int nt = 0; nt < 8; nt++) {
                o[nt][0] *= al_a; o[nt][1] *= al_a;
                o[nt][2] *= al_b; o[nt][3] *= al_b;
            }

            // P -> SMEM (tf32), own-warp region only
            unsigned* Pa = (unsigned*)(Ps + (warp * 16 + gid) * FB);
            unsigned* Pb = (unsigned*)(Ps + (warp * 16 + gid + 8) * FB);
            #pragma unroll
            for (int nt = 0; nt < 8; nt++) {
                int c = nt * 8 + 2 * tig;
                Pa[c]     = f2tf32(s[nt][0]);
                Pa[c + 1] = f2tf32(s[nt][1]);
                Pb[c]     = f2tf32(s[nt][2]);
                Pb[c + 1] = f2tf32(s[nt][3]);
            }
            __syncwarp();

            // O += P V
            #pragma unroll
            for (int ks = 0; ks < 8; ks++) {
                unsigned af[4];
                af[0] = ((const unsigned*)Pa)[ks * 8 + tig];
                af[1] = ((const unsigned*)Pb)[ks * 8 + tig];
                af[2] = ((const unsigned*)Pa)[ks * 8 + tig + 4];
                af[3] = ((const unsigned*)Pb)[ks * 8 + tig + 4];
                #pragma unroll
                for (int nt = 0; nt < 8; nt++) {
                    const unsigned* Vp = (const unsigned*)(Vt + (nt * 8 + gid) * FB + ks * 8);
                    unsigned bf[2] = { Vp[tig], Vp[tig + 4] };
                    mma_tf32(o[nt], af, bf);
                }
            }
        }
        __syncthreads();
    }

    // normalize + write O
    float ia = 1.0f / l_a, ib = 1.0f / l_b;
    #pragma unroll
    for (int nt = 0; nt < 8; nt++) {
        int d = nt * 8 + 2 * tig;
        *(float2*)(g_o + base + (size_t)row_a * ND + d) =
            make_float2(o[nt][0] * ia, o[nt][1] * ia);
        *(float2*)(g_o + base + (size_t)row_b * ND + d) =
            make_float2(o[nt][2] * ib, o[nt][3] * ib);
    }
}

// ---------------------------------------------------------------------------
extern "C" void kernel_launch(void* const* d_in, const int* in_sizes, int n_in,
                              void* d_out, int out_size) {
    const float* x  = (const float*)d_in[0];
    // d_in[1] = mask (bool tril) -- causality is hardcoded
    const float* wq = (const float*)d_in[2];
    const float* wk = (const float*)d_in[3];
    const float* wv = (const float*)d_in[4];
    const float* wo = (const float*)d_in[5];
    float* out = (float*)d_out;

    void *pq, *pk, *pv, *po;
    cudaGetSymbolAddress(&pq, g_q);
    cudaGetSymbolAddress(&pk, g_k);
    cudaGetSymbolAddress(&pv, g_v);
    cudaGetSymbolAddress(&po, g_o);

    cudaFuncSetAttribute(flash_tc_kernel,
                         cudaFuncAttributeMaxDynamicSharedMemorySize, FA2_SMEM);

    rope_table_kernel<<<(NS * 32 + 255) / 256, 256>>>();

    dim3 gg(ND / 128, NM / 128);
    gemm_tc<1><<<gg, 256>>>(x, wq, (float*)pq);
    gemm_tc<1><<<gg, 256>>>(x, wk, (float*)pk);
    gemm_tc<0><<<gg, 256>>>(x, wv, (float*)pv);

    flash_tc_kernel<<<dim3(NS / 128, NH, NB), 256, FA2_SMEM>>>();

    gemm_tc<0><<<gg, 256>>>((const float*)po, wo, out);
}